// round 12
// baseline (speedup 1.0000x reference)
#include <cuda_runtime.h>

#define NA      102000
#define NFEAT   85
#define NC      80
#define KSEL    8192
#define CAP     16384
#define MAXDET  300
#define CONF    0.25f
#define IOUT    0.45f
#define MWORDS  256     // KSEL/32
#define NBLK    8       // KSEL/1024
#define NB      148     // persistent blocks (1 per SM, co-resident)
#define NT      1024
#define SMEM_BYTES 168960   // P6: 8448*16 (boxes f4, pitch-33) + 8448*4 (areas)
#define WTOT    1052672     // total upper-triangle (row,word) units: sum_g 32*(256-g)

// ---------------- device scratch (zero-init at load; invariants restored per call) ----
__device__ unsigned int       g_arrive;
__device__ unsigned int       g_keys[NA];
__device__ unsigned int       g_hist1[65536];
__device__ unsigned int       g_off[65536];     // bucket suffix offsets (written where used)
__device__ unsigned int       g_bcnt[65536];
__device__ unsigned int       g_T;
__device__ unsigned int       g_cnt;
__device__ unsigned long long g_surv[CAP];
__device__ float4             g_top_box[KSEL];
__device__ float              g_top_area[KSEL];
__device__ float              g_top_score[KSEL];
__device__ float              g_top_cls[KSEL];
__device__ unsigned int       g_mask[KSEL * MWORDS];   // sub-diagonal words never written: stay 0 == reference semantics (i suppresses only j>i)

// grid-wide barrier: all NB blocks co-resident; epoch e = barrier ordinal (1-based)
__device__ __forceinline__ void gbar(unsigned e) {
    __syncthreads();
    if (threadIdx.x == 0) {
        __threadfence();
        atomicAdd(&g_arrive, 1u);
        unsigned target = e * NB;
        while (atomicAdd(&g_arrive, 0u) < target) __nanosleep(64);
        __threadfence();
    }
    __syncthreads();
}

// cumulative units before row-group g: C(g) = 8208g - 16g^2
__device__ __forceinline__ int Cg(int g) { return 8208 * g - 16 * g * g; }

extern "C" __global__ void __launch_bounds__(NT, 1)
yolo_all(const float* __restrict__ preds, float* __restrict__ out, int n) {
    extern __shared__ char dsm[];
    __shared__ int s_C, s_B;
    __shared__ int kept[MAXDET];
    __shared__ unsigned blocksup[32];
    __shared__ int s_kept, s_skip;

    int tid = threadIdx.x;
    int blk = blockIdx.x;
    int g = blk * NT + tid;

    // ---- P0: zero per-call state ----
    if (g < 65536) { g_hist1[g] = 0u; g_bcnt[g] = 0u; }
    if (g < KSEL)  g_top_score[g] = 0.f;
    gbar(1);

    // ---- P1: scores via fmax tree (max commutes with *obj for obj>0), coarse hist ----
    {
        float*  sf  = (float*)dsm;
        float4* sf4 = (float4*)dsm;
        int ntile = (n + 255) / 256;
        for (int tile = blk; tile < ntile; tile += NB) {
            int base = tile * 256;
            int cnt_t = n - base; if (cnt_t > 256) cnt_t = 256;
            int nel = cnt_t * NFEAT;
            int nel4 = nel >> 2;
            const float*  src  = preds + (size_t)base * NFEAT;
            const float4* src4 = (const float4*)src;      // base*85*4 % 16 == 0
            __syncthreads();
            for (int i = tid; i < nel4; i += NT) sf4[i] = src4[i];
            for (int i = (nel4 << 2) + tid; i < nel; i += NT) sf[i] = src[i];
            __syncthreads();
            if (tid < cnt_t) {
                const float* p = &sf[tid * NFEAT];        // stride 85: conflict-free
                float obj = p[4];
                float m = p[5];
                #pragma unroll
                for (int c = 1; c < NC; c++) m = fmaxf(m, p[5 + c]);
                float score = (obj > CONF) ? __fmul_rn(m, obj) : 0.0f;
                unsigned key = __float_as_uint(score);
                g_keys[base + tid] = key;
                if (key) atomicAdd(&g_hist1[key >> 16], 1u);
            }
        }
    }
    gbar(2);

    // ---- P2 (block 0): coarse bucket Bc, T, bucket suffix offsets g_off, g_cnt ----
    if (blk == 0) {
        unsigned* sv = (unsigned*)dsm;           // [0..1024): chunk suffix (level A)
        unsigned* sw = sv + 1024;                // [1024..2048): scan ping buffer
        unsigned* sb0 = sw + 1024;               // level-B buffers (64 each)
        unsigned* sb1 = sb0 + 64;
        // level A: 1024 chunks of 64 buckets
        unsigned sum = 0;
        {
            const unsigned* h = g_hist1 + tid * 64;
            #pragma unroll 8
            for (int k = 0; k < 64; k++) sum += h[k];
        }
        sv[tid] = sum; __syncthreads();
        {
            unsigned* src = sv; unsigned* dst = sw;
            #pragma unroll
            for (int d = 1; d < 1024; d <<= 1) {
                unsigned x = src[tid];
                if (tid + d < 1024) x += src[tid + d];
                dst[tid] = x; __syncthreads();
                unsigned* t2 = src; src = dst; dst = t2;
            }   // 10 swaps -> inclusive suffix in sv
        }
        if (tid == 0) s_C = -1;
        __syncthreads();
        if (sv[tid] >= (unsigned)KSEL) atomicMax(&s_C, tid);
        __syncthreads();
        int C = s_C;
        unsigned exclC = (C >= 0 && C < 1023) ? sv[C + 1] : 0u;
        int Bc = 0;
        if (C >= 0) {
            if (tid < 64) sb0[tid] = g_hist1[C * 64 + tid];
            __syncthreads();
            unsigned* sa = sb0; unsigned* sb = sb1;
            #pragma unroll
            for (int d = 1; d < 64; d <<= 1) {
                unsigned x = 0;
                if (tid < 64) { x = sa[tid]; if (tid + d < 64) x += sa[tid + d]; }
                if (tid < 64) sb[tid] = x;
                __syncthreads();
                unsigned* t2 = sa; sa = sb; sb = t2;
            }   // 6 swaps -> suffix in sb0
            if (tid == 0) s_B = 0;
            __syncthreads();
            unsigned tgt = (unsigned)KSEL - exclC;
            if (tid < 64 && sa[tid] >= tgt) atomicMax(&s_B, tid);
            __syncthreads();
            Bc = C * 64 + s_B;
        }
        unsigned T = ((unsigned)Bc) << 16;
        if (!T) T = 1u;
        if (tid == 0) g_T = T;
        // off walk: only chunks containing buckets >= Bc
        int chunk = tid;
        if ((chunk + 1) * 64 > Bc) {
            unsigned run = (chunk < 1023) ? sv[chunk + 1] : 0u;
            #pragma unroll 8
            for (int k = 63; k >= 0; k--) {
                int c = chunk * 64 + k;
                unsigned hv = g_hist1[c];
                g_off[c] = run;
                run += hv;
            }
            if ((Bc >> 6) == chunk)
                g_cnt = g_off[Bc] + g_hist1[Bc];   // total survivors (suffix incl. Bc)
        }
    }
    gbar(3);

    // ---- P3: segmented compact into bucket slots (match_any aggregated atomics) ----
    {
        unsigned T = g_T;
        unsigned key = 0; bool pred = false;
        if (g < n) { key = g_keys[g]; pred = (key >= T); }
        unsigned c = pred ? (key >> 16) : 0xFFFFFFFFu;
        unsigned grp = __match_any_sync(0xffffffffu, c);
        int lane = tid & 31;
        int leader = __ffs(grp) - 1;
        unsigned base2 = 0;
        if (pred && lane == leader) base2 = atomicAdd(&g_bcnt[c], (unsigned)__popc(grp));
        base2 = __shfl_sync(0xffffffffu, base2, leader);
        if (pred) {
            unsigned slot = g_off[c] + base2 + (unsigned)__popc(grp & ((1u << lane) - 1u));
            if (slot < CAP)
                g_surv[slot] = ((unsigned long long)key << 32) | (unsigned)(~g);
        }
    }
    gbar(4);

    // ---- P4': within-bucket rank (+bucket offset) + gather, spread across all SMs ----
    {
        unsigned cnt = g_cnt; if (cnt > CAP) cnt = CAP;
        for (unsigned s = (unsigned)(blk + NB * tid); s < cnt; s += (unsigned)(NB * NT)) {
            unsigned long long key = g_surv[s];
            unsigned c = (unsigned)(key >> 48);
            unsigned start = g_off[c];
            unsigned end = start + g_bcnt[c];
            if (end > CAP) end = CAP;
            unsigned r = start;
            #pragma unroll 4
            for (unsigned j = start; j < end; j++)
                r += (g_surv[j] > key) ? 1u : 0u;
            if (r < KSEL) {
                unsigned idx = ~(unsigned)(key & 0xFFFFFFFFu);
                float score = __uint_as_float((unsigned)(key >> 32));
                const float* p = preds + (size_t)idx * NFEAT;
                float x = p[0], y = p[1], w = p[2], h = p[3];
                float hh = __fmul_rn(h, 0.5f), hw = __fmul_rn(w, 0.5f);
                float4 box;
                box.x = __fsub_rn(y, hh);
                box.y = __fsub_rn(x, hw);
                box.z = __fadd_rn(y, hh);
                box.w = __fadd_rn(x, hw);
                float area = __fmul_rn(__fsub_rn(box.z, box.x), __fsub_rn(box.w, box.y));
                float obj = p[4];
                float best = -1.0f; int bi = 0;
                #pragma unroll 4
                for (int cc = 0; cc < NC; cc++) {
                    float v = __fmul_rn(p[5 + cc], obj);   // exact reference argmax order
                    if (v > best) { best = v; bi = cc; }
                }
                g_top_box[r]   = box;
                g_top_area[r]  = area;
                g_top_score[r] = score;
                g_top_cls[r]   = (float)bi;
            }
        }
    }
    gbar(5);

    // ---- P6: suppression bitmask; exact 1-D partition of upper-triangle units ----
    {
        float4* sbox = (float4*)dsm;                 // pitch-33: idx j + (j>>5)
        float*  sare = (float*)(dsm + 8448 * 16);
        for (int j = tid; j < KSEL; j += NT) {
            int sl = j + (j >> 5);
            sbox[sl] = g_top_box[j];
            sare[sl] = g_top_area[j];
        }
        __syncthreads();
        const float BHI = 0.4500045f;   // above -> surely iou>0.45 (margin >> fp32 err)
        const float BLO = 0.4499955f;   // below -> surely not
        int lo = (int)((long long)blk * WTOT / NB);
        int hi = (int)((long long)(blk + 1) * WTOT / NB);
        for (int f = lo + tid; f < hi; f += NT) {
            // unit f -> (row-group gg, row rr, word jw)
            float disc = 67371264.f - 64.f * (float)f;     // 8208^2 - 64f
            int gg = (int)((8208.f - sqrtf(disc)) * 0.03125f);
            if (gg < 0) gg = 0; if (gg > 255) gg = 255;
            while (gg < 255 && Cg(gg + 1) <= f) gg++;
            while (gg > 0 && Cg(gg) > f) gg--;
            int wg = 256 - gg;
            int local = f - Cg(gg);
            int rr = local / wg;
            int jw = gg + (local - rr * wg);
            int row = (gg << 5) + rr;
            int si = row + gg;
            float4 bb = sbox[si];
            float ai = sare[si];
            int sbase = jw * 33;
            unsigned word = 0, band = 0;
            #pragma unroll 8
            for (int b = 0; b < 32; b++) {
                float4 bj = sbox[sbase + b];
                float ty  = fmaxf(bb.x, bj.x);
                float tx  = fmaxf(bb.y, bj.y);
                float byv = fminf(bb.z, bj.z);
                float bxv = fminf(bb.w, bj.w);
                float ih = fmaxf(__fsub_rn(byv, ty), 0.f);
                float iw = fmaxf(__fsub_rn(bxv, tx), 0.f);
                float inter = __fmul_rn(ih, iw);
                float den = __fadd_rn(__fsub_rn(__fadd_rn(ai, sare[sbase + b]), inter), 1e-9f);
                bool hiq = inter > __fmul_rn(BHI, den);
                bool bd = !hiq && (inter > __fmul_rn(BLO, den));
                word |= hiq ? (1u << b) : 0u;
                band |= bd ? (1u << b) : 0u;
            }
            if (jw == gg) {                              // diagonal word: only j > row
                unsigned diagm = 0xFFFFFFFEu << (row & 31);
                word &= diagm; band &= diagm;
            }
            if (band) {   // essentially never: exact division for ambiguous pairs
                while (band) {
                    int b = __ffs(band) - 1; band &= band - 1;
                    float4 bj = sbox[sbase + b];
                    float ty  = fmaxf(bb.x, bj.x);
                    float tx  = fmaxf(bb.y, bj.y);
                    float byv = fminf(bb.z, bj.z);
                    float bxv = fminf(bb.w, bj.w);
                    float ih = fmaxf(__fsub_rn(byv, ty), 0.f);
                    float iw = fmaxf(__fsub_rn(bxv, tx), 0.f);
                    float inter = __fmul_rn(ih, iw);
                    float den = __fadd_rn(__fsub_rn(__fadd_rn(ai, sare[sbase + b]), inter), 1e-9f);
                    if (__fdiv_rn(inter, den) > IOUT) word |= (1u << b);
                }
            }
            g_mask[(size_t)row * MWORDS + jw] = word;
        }
    }
    gbar(6);

    // ---- P7: hierarchical greedy scan + output (block 0; others exit) ----
    if (blk != 0) return;
    {
        unsigned* sm = (unsigned*)dsm;              // 128 KB
        int warp = tid >> 5, lane = tid & 31;
        if (tid == 0) s_kept = 0;
        __syncthreads();
        for (int b = 0; b < NBLK; b++) {
            if (s_kept >= MAXDET) break;
            {
                float s = g_top_score[b * 1024 + warp * 32 + lane];
                unsigned inval = __ballot_sync(0xffffffffu, !(s > 0.f));
                unsigned v = 0;
                int nk = s_kept;
                for (int k = lane; k < nk; k += 32)
                    v |= g_mask[(size_t)kept[k] * MWORDS + b * 32 + warp];
                v = __reduce_or_sync(0xffffffffu, v) | inval;
                if (lane == 0) blocksup[warp] = v;
            }
            __syncthreads();
            if (tid < 32) {
                unsigned v = blocksup[lane];
                unsigned full = __ballot_sync(0xffffffffu, v == 0xFFFFFFFFu);
                if (lane == 0) s_skip = (full == 0xFFFFFFFFu) ? 1 : 0;
            }
            __syncthreads();
            if (s_skip) continue;
            for (int u = tid; u < 8192; u += 1024) {
                int i = u >> 3, w4 = u & 7;
                ((uint4*)sm)[u] =
                    ((const uint4*)(g_mask + (size_t)(b * 1024 + i) * MWORDS + b * 32))[w4];
            }
            __syncthreads();
            if (tid < 32) {
                unsigned sup_w = blocksup[lane];
                int cnt = s_kept;
                while (cnt < MAXDET) {
                    unsigned live = ~sup_w;
                    int cand = live ? ((lane << 5) + __ffs(live) - 1) : 0x7FFFFFFF;
                    int li = __reduce_min_sync(0xffffffffu, cand);
                    if (li == 0x7FFFFFFF) break;
                    if (lane == 0) kept[cnt] = b * 1024 + li;
                    cnt++;
                    if (lane == (li >> 5)) sup_w |= (1u << (li & 31));   // mark processed
                    sup_w |= sm[li * 32 + lane];                        // row OR
                }
                if (lane == 0) s_kept = cnt;
            }
            __syncthreads();
        }
        int m = s_kept;
        for (int t = tid; t < MAXDET; t += 1024) {
            float4 bx = make_float4(0.f, 0.f, 0.f, 0.f);
            float c = 0.f, s = 0.f;
            if (t < m) {
                int ki = kept[t];
                bx = g_top_box[ki];
                c = g_top_cls[ki];
                s = g_top_score[ki];
            }
            out[4 * t + 0] = bx.x; out[4 * t + 1] = bx.y;
            out[4 * t + 2] = bx.z; out[4 * t + 3] = bx.w;
            out[1200 + t] = c;
            out[1500 + t] = s;
        }
        __syncthreads();
        if (tid == 0) g_arrive = 0u;   // reset barrier for next (graph-replayed) call
    }
}

// ---------------- launch: ONE kernel node ----------------
extern "C" void kernel_launch(void* const* d_in, const int* in_sizes, int n_in,
                              void* d_out, int out_size) {
    const float* preds = (const float*)d_in[0];
    float* out = (float*)d_out;
    int n = in_sizes[0] / NFEAT;
    if (n > NA) n = NA;

    cudaFuncSetAttribute(yolo_all, cudaFuncAttributeMaxDynamicSharedMemorySize, SMEM_BYTES);
    yolo_all<<<NB, NT, SMEM_BYTES>>>(preds, out, n);
}

// round 13
// speedup vs baseline: 1.5415x; 1.5415x over previous
#include <cuda_runtime.h>

#define NA      102000
#define NFEAT   85
#define NC      80
#define KSEL    8192
#define CAP     16384
#define MAXDET  300
#define CONF    0.25f
#define IOUT    0.45f
#define MWORDS  256     // KSEL/32
#define NBLK    8       // KSEL/1024
#define NB      148     // persistent blocks (1 per SM, co-resident)
#define NT      1024
#define SMEM_BYTES 168960   // P6: 8448*16 (boxes f4, pitch-33) + 8448*4 (areas)

// ---------------- device scratch (zero-init at load; invariants restored per call) ----
__device__ unsigned int       g_arrive;
__device__ unsigned int       g_keys[NA];
__device__ unsigned int       g_hist1[65536];
__device__ unsigned int       g_T;
__device__ unsigned int       g_cnt;
__device__ unsigned long long g_surv[CAP];
__device__ int                g_rank[CAP];
__device__ float4             g_top_box[KSEL];
__device__ float              g_top_area[KSEL];
__device__ float              g_top_score[KSEL];
__device__ float              g_top_cls[KSEL];
__device__ unsigned int       g_mask[KSEL * MWORDS];   // sub-diagonal words never written: stay 0

// grid-wide barrier: all NB blocks co-resident; epoch e = barrier ordinal (1-based)
__device__ __forceinline__ void gbar(unsigned e) {
    __syncthreads();
    if (threadIdx.x == 0) {
        __threadfence();
        atomicAdd(&g_arrive, 1u);
        unsigned target = e * NB;
        while (atomicAdd(&g_arrive, 0u) < target) __nanosleep(64);
        __threadfence();
    }
    __syncthreads();
}

// 256-wide suffix-sum select (tid<256 carry data); final inclusive suffix left in sA
__device__ __forceinline__ int suffix_sel_1024(unsigned* sA, unsigned* sB, int* sres,
                                               int tid, unsigned v, unsigned target) {
    if (tid < 256) sA[tid] = v;
    __syncthreads();
    unsigned* src = sA; unsigned* dst = sB;
    #pragma unroll
    for (int d = 1; d < 256; d <<= 1) {
        unsigned x = 0;
        if (tid < 256) { x = src[tid]; if (tid + d < 256) x += src[tid + d]; }
        if (tid < 256) dst[tid] = x;
        __syncthreads();
        unsigned* t2 = src; src = dst; dst = t2;
    }   // 8 swaps -> suffix back in sA
    if (tid == 0) *sres = -1;
    __syncthreads();
    if (tid < 256 && sA[tid] >= target) atomicMax(sres, tid);
    __syncthreads();
    return *sres;
}

extern "C" __global__ void __launch_bounds__(NT, 1)
yolo_all(const float* __restrict__ preds, float* __restrict__ out, int n) {
    extern __shared__ char dsm[];
    __shared__ unsigned s_sA[256], s_sB[256];
    __shared__ int s_res;
    __shared__ int kept[MAXDET];
    __shared__ unsigned blocksup[32];
    __shared__ int s_kept, s_skip;

    int tid = threadIdx.x;
    int blk = blockIdx.x;
    int g = blk * NT + tid;

    // ---- P0: zero state (replay-idempotent) ----
    if (g < 65536) g_hist1[g] = 0u;
    if (g < CAP)   g_rank[g] = 0;
    if (g < KSEL)  g_top_score[g] = 0.f;
    if (g == 0)    g_cnt = 0u;
    gbar(1);

    // ---- P1: scores via fmax tree (max commutes with *obj for obj>0), coarse hist ----
    {
        float*  sf  = (float*)dsm;
        float4* sf4 = (float4*)dsm;
        int ntile = (n + 255) / 256;
        for (int tile = blk; tile < ntile; tile += NB) {
            int base = tile * 256;
            int cnt_t = n - base; if (cnt_t > 256) cnt_t = 256;
            int nel = cnt_t * NFEAT;
            int nel4 = nel >> 2;
            const float*  src  = preds + (size_t)base * NFEAT;
            const float4* src4 = (const float4*)src;      // base*85*4 % 16 == 0
            __syncthreads();
            for (int i = tid; i < nel4; i += NT) sf4[i] = src4[i];
            for (int i = (nel4 << 2) + tid; i < nel; i += NT) sf[i] = src[i];
            __syncthreads();
            if (tid < cnt_t) {
                const float* p = &sf[tid * NFEAT];        // stride 85: conflict-free
                float obj = p[4];
                float m = p[5];
                #pragma unroll
                for (int c = 1; c < NC; c++) m = fmaxf(m, p[5 + c]);
                float score = (obj > CONF) ? __fmul_rn(m, obj) : 0.0f;
                unsigned key = __float_as_uint(score);
                g_keys[base + tid] = key;
                if (key) atomicAdd(&g_hist1[key >> 16], 1u);
            }
        }
    }
    gbar(2);

    // ---- P2: coarse threshold bucket -> g_T (block 0 only) ----
    if (blk == 0) {
        unsigned s = 0;
        if (tid < 256) {
            const unsigned* h = g_hist1 + tid * 256;
            #pragma unroll 8
            for (int b = 0; b < 256; b++) s += h[b];
        }
        int C = suffix_sel_1024(s_sA, s_sB, &s_res, tid, s, KSEL);
        unsigned T;
        if (C < 0) {
            T = 1u;                               // fewer than KSEL positives: take all
        } else {
            unsigned A1 = (C < 255) ? s_sA[C + 1] : 0u;
            __syncthreads();
            unsigned e = (tid < 256) ? g_hist1[C * 256 + tid] : 0u;
            int b = suffix_sel_1024(s_sA, s_sB, &s_res, tid, e, (unsigned)KSEL - A1);
            T = ((unsigned)(C * 256 + b)) << 16;
            if (!T) T = 1u;                       // never admit score==0
        }
        if (tid == 0) g_T = T;
    }
    gbar(3);

    // ---- P3: compact survivors (coarse superset of top-K), warp-aggregated ----
    {
        unsigned T = g_T;
        bool pred = false; unsigned key = 0;
        if (g < n) { key = g_keys[g]; pred = (key >= T); }
        unsigned m = __ballot_sync(0xffffffffu, pred);
        if (m) {
            int lane = tid & 31;
            int leader = __ffs(m) - 1;
            unsigned base2 = 0;
            if (lane == leader) base2 = atomicAdd(&g_cnt, (unsigned)__popc(m));
            base2 = __shfl_sync(0xffffffffu, base2, leader);
            if (pred) {
                unsigned pos = base2 + (unsigned)__popc(m & ((1u << lane) - 1u));
                if (pos < CAP)
                    g_surv[pos] = ((unsigned long long)key << 32) | (unsigned)(~g);
            }
        }
    }
    gbar(4);

    // ---- P4: exact global rank; quarter-j tiles for wave balance ----
    {
        unsigned long long* sk = (unsigned long long*)dsm;   // 2 KB
        unsigned cnt = g_cnt; if (cnt > CAP) cnt = CAP;
        int njt = ((int)cnt + 1023) >> 10;
        int nbt = njt * njt * 4;
        for (int bt = blk; bt < nbt; bt += NB) {
            int task = bt >> 2, q = bt & 3;
            int ic = task / njt, jc = task - ic * njt;
            int i0 = ic << 10;
            int j0 = (jc << 10) + (q << 8);
            __syncthreads();
            if (tid < 256) {
                int j = j0 + tid;
                sk[tid] = (j < (int)cnt) ? g_surv[j] : 0ULL;   // 0 never > any key
            }
            __syncthreads();
            int i = i0 + tid;
            if (i < (int)cnt) {
                unsigned long long key = g_surv[i];
                const ulonglong2* sk2 = (const ulonglong2*)sk;
                int c0 = 0, c1 = 0;
                #pragma unroll 8
                for (int u = 0; u < 128; u++) {
                    ulonglong2 v = sk2[u];
                    c0 += (v.x > key) ? 1 : 0;
                    c1 += (v.y > key) ? 1 : 0;
                }
                atomicAdd(&g_rank[i], c0 + c1);
            }
        }
    }
    gbar(5);

    // ---- P5: scatter to rank (<KSEL) + gather box/area/score + exact argmax ----
    {
        unsigned cnt = g_cnt; if (cnt > CAP) cnt = CAP;
        for (int c = blk; c * 256 < (int)cnt; c += NB) {
            int i = c * 256 + tid;
            if (tid < 256 && i < (int)cnt) {
                int r = g_rank[i];
                if (r < KSEL) {
                    unsigned long long key = g_surv[i];
                    unsigned idx = ~(unsigned)(key & 0xFFFFFFFFu);
                    float score = __uint_as_float((unsigned)(key >> 32));
                    const float* p = preds + (size_t)idx * NFEAT;
                    float x = p[0], y = p[1], w = p[2], h = p[3];
                    float hh = __fmul_rn(h, 0.5f), hw = __fmul_rn(w, 0.5f);
                    float4 box;
                    box.x = __fsub_rn(y, hh);
                    box.y = __fsub_rn(x, hw);
                    box.z = __fadd_rn(y, hh);
                    box.w = __fadd_rn(x, hw);
                    float area = __fmul_rn(__fsub_rn(box.z, box.x), __fsub_rn(box.w, box.y));
                    float obj = p[4];
                    float best = -1.0f; int bi = 0;
                    #pragma unroll 4
                    for (int cc = 0; cc < NC; cc++) {
                        float v = __fmul_rn(p[5 + cc], obj);   // exact reference argmax order
                        if (v > best) { best = v; bi = cc; }
                    }
                    g_top_box[r]   = box;
                    g_top_area[r]  = area;
                    g_top_score[r] = score;
                    g_top_cls[r]   = (float)bi;
                }
            }
        }
    }
    gbar(6);

    // ---- P6: suppression bitmask; lanes = rows, broadcast j loads, paired groups ----
    if (blk < 128) {
        float4* sbox = (float4*)dsm;                 // pitch-33 (per 32): idx j + (j>>5)
        float*  sare = (float*)(dsm + 8448 * 16);
        for (int j = tid; j < KSEL; j += NT) {
            int sl = j + (j >> 5);
            sbox[sl] = g_top_box[j];
            sare[sl] = g_top_area[j];
        }
        __syncthreads();
        const float BHI = 0.4500045f;   // above -> surely iou>0.45 (margin >> fp32 err)
        const float BLO = 0.4499955f;   // below -> surely not
        int warp = tid >> 5, lane = tid & 31;
        #pragma unroll
        for (int sel = 0; sel < 2; sel++) {
            int grp = sel ? (255 - blk) : blk;       // row group (32 rows)
            int row = (grp << 5) + lane;             // lane = row
            int si = row + grp;
            float4 bb = sbox[si];                    // per-lane (distinct, conflict-free)
            float ai = sare[si];
            int wg = 256 - grp;                      // word columns for this group
            for (int w = warp; w < wg; w += 32) {
                int jw = grp + w;
                int sbase = jw * 33;
                unsigned word = 0, band = 0;
                #pragma unroll 8
                for (int b = 0; b < 32; b++) {
                    float4 bj = sbox[sbase + b];     // uniform -> broadcast
                    float aj = sare[sbase + b];      // broadcast
                    float ty  = fmaxf(bb.x, bj.x);
                    float tx  = fmaxf(bb.y, bj.y);
                    float byv = fminf(bb.z, bj.z);
                    float bxv = fminf(bb.w, bj.w);
                    float ih = fmaxf(__fsub_rn(byv, ty), 0.f);
                    float iw = fmaxf(__fsub_rn(bxv, tx), 0.f);
                    float inter = __fmul_rn(ih, iw);
                    float den = __fadd_rn(__fsub_rn(__fadd_rn(ai, aj), inter), 1e-9f);
                    bool hi = inter > __fmul_rn(BHI, den);
                    bool bd = !hi && (inter > __fmul_rn(BLO, den));
                    word |= hi ? (1u << b) : 0u;
                    band |= bd ? (1u << b) : 0u;
                }
                if (jw == grp) {                     // diagonal word: j>row <=> b>lane
                    unsigned diagm = 0xFFFFFFFEu << lane;
                    word &= diagm; band &= diagm;
                }
                if (band) {   // essentially never: exact division for ambiguous pairs
                    while (band) {
                        int b = __ffs(band) - 1; band &= band - 1;
                        float4 bj = sbox[sbase + b];
                        float aj = sare[sbase + b];
                        float ty  = fmaxf(bb.x, bj.x);
                        float tx  = fmaxf(bb.y, bj.y);
                        float byv = fminf(bb.z, bj.z);
                        float bxv = fminf(bb.w, bj.w);
                        float ih = fmaxf(__fsub_rn(byv, ty), 0.f);
                        float iw = fmaxf(__fsub_rn(bxv, tx), 0.f);
                        float inter = __fmul_rn(ih, iw);
                        float den = __fadd_rn(__fsub_rn(__fadd_rn(ai, aj), inter), 1e-9f);
                        if (__fdiv_rn(inter, den) > IOUT) word |= (1u << b);
                    }
                }
                g_mask[(size_t)row * MWORDS + jw] = word;
            }
        }
    }
    gbar(7);

    // ---- P7: hierarchical greedy scan, paired-keep rounds + output (block 0) ----
    if (blk != 0) return;
    {
        unsigned* sm = (unsigned*)dsm;              // 128 KB
        int warp = tid >> 5, lane = tid & 31;
        if (tid == 0) s_kept = 0;
        __syncthreads();
        for (int b = 0; b < NBLK; b++) {
            if (s_kept >= MAXDET) break;
            {
                float s = g_top_score[b * 1024 + warp * 32 + lane];
                unsigned inval = __ballot_sync(0xffffffffu, !(s > 0.f));
                unsigned v = 0;
                int nk = s_kept;
                for (int k = lane; k < nk; k += 32)
                    v |= g_mask[(size_t)kept[k] * MWORDS + b * 32 + warp];
                v = __reduce_or_sync(0xffffffffu, v) | inval;
                if (lane == 0) blocksup[warp] = v;
            }
            __syncthreads();
            if (tid < 32) {
                unsigned v = blocksup[lane];
                unsigned full = __ballot_sync(0xffffffffu, v == 0xFFFFFFFFu);
                if (lane == 0) s_skip = (full == 0xFFFFFFFFu) ? 1 : 0;
            }
            __syncthreads();
            if (s_skip) continue;
            for (int u = tid; u < 8192; u += 1024) {
                int i = u >> 3, w4 = u & 7;
                ((uint4*)sm)[u] =
                    ((const uint4*)(g_mask + (size_t)(b * 1024 + i) * MWORDS + b * 32))[w4];
            }
            __syncthreads();
            if (tid < 32) {
                unsigned sup_w = blocksup[lane];
                int cnt = s_kept;
                while (cnt < MAXDET) {
                    unsigned live = ~sup_w;
                    unsigned bal = __ballot_sync(0xffffffffu, live != 0u);
                    if (!bal) break;
                    int l = __ffs(bal) - 1;
                    unsigned lw = __shfl_sync(0xffffffffu, live, l);
                    int li = (l << 5) + __ffs(lw) - 1;
                    // second live candidate (pre-OR bitmap)
                    unsigned live2 = live;
                    if (lane == l) live2 &= ~(1u << (li & 31));
                    unsigned bal2 = __ballot_sync(0xffffffffu, live2 != 0u);
                    int lj = -1;
                    if (bal2) {
                        int l2 = __ffs(bal2) - 1;
                        unsigned lw2 = __shfl_sync(0xffffffffu, live2, l2);
                        lj = (l2 << 5) + __ffs(lw2) - 1;
                    }
                    unsigned rowi = sm[li * 32 + lane];
                    bool pairok = false;
                    if (lj >= 0 && cnt + 1 < MAXDET) {
                        // bit lj of mask row li: held by lane (lj>>5)
                        unsigned wv = __shfl_sync(0xffffffffu, rowi, lj >> 5);
                        pairok = ((wv >> (lj & 31)) & 1u) == 0u;
                    }
                    if (pairok) {
                        // lj provably the next sequential keep after li
                        unsigned rowj = sm[lj * 32 + lane];
                        if (lane == 0) { kept[cnt] = b * 1024 + li; kept[cnt + 1] = b * 1024 + lj; }
                        cnt += 2;
                        sup_w |= rowi | rowj;
                        if (lane == (li >> 5)) sup_w |= (1u << (li & 31));
                        if (lane == (lj >> 5)) sup_w |= (1u << (lj & 31));
                    } else {
                        if (lane == 0) kept[cnt] = b * 1024 + li;
                        cnt++;
                        sup_w |= rowi;
                        if (lane == (li >> 5)) sup_w |= (1u << (li & 31));
                    }
                }
                if (lane == 0) s_kept = cnt;
            }
            __syncthreads();
        }
        int m = s_kept;
        for (int t = tid; t < MAXDET; t += 1024) {
            float4 bx = make_float4(0.f, 0.f, 0.f, 0.f);
            float c = 0.f, s = 0.f;
            if (t < m) {
                int ki = kept[t];
                bx = g_top_box[ki];
                c = g_top_cls[ki];
                s = g_top_score[ki];
            }
            out[4 * t + 0] = bx.x; out[4 * t + 1] = bx.y;
            out[4 * t + 2] = bx.z; out[4 * t + 3] = bx.w;
            out[1200 + t] = c;
            out[1500 + t] = s;
        }
        __syncthreads();
        if (tid == 0) g_arrive = 0u;   // reset barrier for next (graph-replayed) call
    }
}

// ---------------- launch: ONE kernel node ----------------
extern "C" void kernel_launch(void* const* d_in, const int* in_sizes, int n_in,
                              void* d_out, int out_size) {
    const float* preds = (const float*)d_in[0];
    float* out = (float*)d_out;
    int n = in_sizes[0] / NFEAT;
    if (n > NA) n = NA;

    cudaFuncSetAttribute(yolo_all, cudaFuncAttributeMaxDynamicSharedMemorySize, SMEM_BYTES);
    yolo_all<<<NB, NT, SMEM_BYTES>>>(preds, out, n);
}

// round 14
// speedup vs baseline: 1.7604x; 1.1420x over previous
#include <cuda_runtime.h>

#define NA      102000
#define NFEAT   85
#define NC      80
#define KSEL    8192
#define CAP     16384
#define MAXDET  300
#define CONF    0.25f
#define IOUT    0.45f
#define MWORDS  256     // KSEL/32
#define NBLK    8       // KSEL/1024
#define NB      148     // persistent blocks (1 per SM, co-resident)
#define NT      1024
#define SMEM_BYTES 131072

// ---------------- device scratch (zero-init at load; invariants restored per call) ----
__device__ unsigned int       g_arrive;
__device__ unsigned int       g_keys[NA];
__device__ unsigned int       g_hist1[65536];
__device__ unsigned int       g_T;
__device__ unsigned int       g_cnt;
__device__ unsigned int       g_nk;             // kept count so far (cross-SM)
__device__ unsigned int       g_done;
__device__ unsigned int       g_kept[MAXDET];   // kept rows, in keep order
__device__ unsigned long long g_surv[CAP];
__device__ int                g_rank[CAP];
__device__ float4             g_top_box[KSEL];
__device__ float              g_top_area[KSEL];
__device__ float              g_top_score[KSEL];
__device__ float              g_top_cls[KSEL];
__device__ unsigned int       g_mask[KSEL * MWORDS];   // only demanded words ever written; sub-diagonal words stay 0

// grid-wide barrier: all NB blocks co-resident; epoch e = barrier ordinal (1-based)
__device__ __forceinline__ void gbar(unsigned e) {
    __syncthreads();
    if (threadIdx.x == 0) {
        __threadfence();
        atomicAdd(&g_arrive, 1u);
        unsigned target = e * NB;
        while (atomicAdd(&g_arrive, 0u) < target) __nanosleep(64);
        __threadfence();
    }
    __syncthreads();
}

// 256-wide suffix-sum select (tid<256 carry data); final inclusive suffix left in sA
__device__ __forceinline__ int suffix_sel_1024(unsigned* sA, unsigned* sB, int* sres,
                                               int tid, unsigned v, unsigned target) {
    if (tid < 256) sA[tid] = v;
    __syncthreads();
    unsigned* src = sA; unsigned* dst = sB;
    #pragma unroll
    for (int d = 1; d < 256; d <<= 1) {
        unsigned x = 0;
        if (tid < 256) { x = src[tid]; if (tid + d < 256) x += src[tid + d]; }
        if (tid < 256) dst[tid] = x;
        __syncthreads();
        unsigned* t2 = src; src = dst; dst = t2;
    }   // 8 swaps -> suffix back in sA
    if (tid == 0) *sres = -1;
    __syncthreads();
    if (tid < 256 && sA[tid] >= target) atomicMax(sres, tid);
    __syncthreads();
    return *sres;
}

extern "C" __global__ void __launch_bounds__(NT, 1)
yolo_all(const float* __restrict__ preds, float* __restrict__ out, int n) {
    extern __shared__ char dsm[];
    __shared__ unsigned s_sA[256], s_sB[256];
    __shared__ int s_res;
    __shared__ int kept[MAXDET];
    __shared__ unsigned blocksup[32];
    __shared__ int s_kept, s_skip, s_prev;

    int tid = threadIdx.x;
    int blk = blockIdx.x;
    int g = blk * NT + tid;

    // ---- P0: zero state (replay-idempotent) ----
    if (g < 65536) g_hist1[g] = 0u;
    if (g < CAP)   g_rank[g] = 0;
    if (g < KSEL)  g_top_score[g] = 0.f;
    if (g == 0)    { g_cnt = 0u; g_nk = 0u; g_done = 0u; }
    gbar(1);

    // ---- P1: scores via fmax tree (max commutes with *obj for obj>0), coarse hist ----
    {
        float*  sf  = (float*)dsm;
        float4* sf4 = (float4*)dsm;
        int ntile = (n + 255) / 256;
        for (int tile = blk; tile < ntile; tile += NB) {
            int base = tile * 256;
            int cnt_t = n - base; if (cnt_t > 256) cnt_t = 256;
            int nel = cnt_t * NFEAT;
            int nel4 = nel >> 2;
            const float*  src  = preds + (size_t)base * NFEAT;
            const float4* src4 = (const float4*)src;      // base*85*4 % 16 == 0
            __syncthreads();
            for (int i = tid; i < nel4; i += NT) sf4[i] = src4[i];
            for (int i = (nel4 << 2) + tid; i < nel; i += NT) sf[i] = src[i];
            __syncthreads();
            if (tid < cnt_t) {
                const float* p = &sf[tid * NFEAT];        // stride 85: conflict-free
                float obj = p[4];
                float m = p[5];
                #pragma unroll
                for (int c = 1; c < NC; c++) m = fmaxf(m, p[5 + c]);
                float score = (obj > CONF) ? __fmul_rn(m, obj) : 0.0f;
                unsigned key = __float_as_uint(score);
                g_keys[base + tid] = key;
                if (key) atomicAdd(&g_hist1[key >> 16], 1u);
            }
        }
    }
    gbar(2);

    // ---- P2: coarse threshold bucket -> g_T (block 0 only) ----
    if (blk == 0) {
        unsigned s = 0;
        if (tid < 256) {
            const unsigned* h = g_hist1 + tid * 256;
            #pragma unroll 8
            for (int b = 0; b < 256; b++) s += h[b];
        }
        int C = suffix_sel_1024(s_sA, s_sB, &s_res, tid, s, KSEL);
        unsigned T;
        if (C < 0) {
            T = 1u;                               // fewer than KSEL positives: take all
        } else {
            unsigned A1 = (C < 255) ? s_sA[C + 1] : 0u;
            __syncthreads();
            unsigned e = (tid < 256) ? g_hist1[C * 256 + tid] : 0u;
            int b = suffix_sel_1024(s_sA, s_sB, &s_res, tid, e, (unsigned)KSEL - A1);
            T = ((unsigned)(C * 256 + b)) << 16;
            if (!T) T = 1u;                       // never admit score==0
        }
        if (tid == 0) g_T = T;
    }
    gbar(3);

    // ---- P3: compact survivors (coarse superset of top-K), warp-aggregated ----
    {
        unsigned T = g_T;
        bool pred = false; unsigned key = 0;
        if (g < n) { key = g_keys[g]; pred = (key >= T); }
        unsigned m = __ballot_sync(0xffffffffu, pred);
        if (m) {
            int lane = tid & 31;
            int leader = __ffs(m) - 1;
            unsigned base2 = 0;
            if (lane == leader) base2 = atomicAdd(&g_cnt, (unsigned)__popc(m));
            base2 = __shfl_sync(0xffffffffu, base2, leader);
            if (pred) {
                unsigned pos = base2 + (unsigned)__popc(m & ((1u << lane) - 1u));
                if (pos < CAP)
                    g_surv[pos] = ((unsigned long long)key << 32) | (unsigned)(~g);
            }
        }
    }
    gbar(4);

    // ---- P4: exact global rank; quarter-j tiles for wave balance ----
    {
        unsigned long long* sk = (unsigned long long*)dsm;   // 2 KB
        unsigned cnt = g_cnt; if (cnt > CAP) cnt = CAP;
        int njt = ((int)cnt + 1023) >> 10;
        int nbt = njt * njt * 4;
        for (int bt = blk; bt < nbt; bt += NB) {
            int task = bt >> 2, q = bt & 3;
            int ic = task / njt, jc = task - ic * njt;
            int i0 = ic << 10;
            int j0 = (jc << 10) + (q << 8);
            __syncthreads();
            if (tid < 256) {
                int j = j0 + tid;
                sk[tid] = (j < (int)cnt) ? g_surv[j] : 0ULL;   // 0 never > any key
            }
            __syncthreads();
            int i = i0 + tid;
            if (i < (int)cnt) {
                unsigned long long key = g_surv[i];
                const ulonglong2* sk2 = (const ulonglong2*)sk;
                int c0 = 0, c1 = 0;
                #pragma unroll 8
                for (int u = 0; u < 128; u++) {
                    ulonglong2 v = sk2[u];
                    c0 += (v.x > key) ? 1 : 0;
                    c1 += (v.y > key) ? 1 : 0;
                }
                atomicAdd(&g_rank[i], c0 + c1);
            }
        }
    }
    gbar(5);

    // ---- P5: scatter to rank (<KSEL) + gather box/area/score + exact argmax ----
    {
        unsigned cnt = g_cnt; if (cnt > CAP) cnt = CAP;
        for (int c = blk; c * 256 < (int)cnt; c += NB) {
            int i = c * 256 + tid;
            if (tid < 256 && i < (int)cnt) {
                int r = g_rank[i];
                if (r < KSEL) {
                    unsigned long long key = g_surv[i];
                    unsigned idx = ~(unsigned)(key & 0xFFFFFFFFu);
                    float score = __uint_as_float((unsigned)(key >> 32));
                    const float* p = preds + (size_t)idx * NFEAT;
                    float x = p[0], y = p[1], w = p[2], h = p[3];
                    float hh = __fmul_rn(h, 0.5f), hw = __fmul_rn(w, 0.5f);
                    float4 box;
                    box.x = __fsub_rn(y, hh);
                    box.y = __fsub_rn(x, hw);
                    box.z = __fadd_rn(y, hh);
                    box.w = __fadd_rn(x, hw);
                    float area = __fmul_rn(__fsub_rn(box.z, box.x), __fsub_rn(box.w, box.y));
                    float obj = p[4];
                    float best = -1.0f; int bi = 0;
                    #pragma unroll 4
                    for (int cc = 0; cc < NC; cc++) {
                        float v = __fmul_rn(p[5 + cc], obj);   // exact reference argmax order
                        if (v > best) { best = v; bi = cc; }
                    }
                    g_top_box[r]   = box;
                    g_top_area[r]  = area;
                    g_top_score[r] = score;
                    g_top_cls[r]   = (float)bi;
                }
            }
        }
    }
    gbar(6);

    // ---- P6/P7 fused: lazy mask + scan, per 1024-block, interleaved ----
    {
        const float BHI = 0.4500045f;   // above -> surely iou>0.45 (margin >> fp32 err)
        const float BLO = 0.4499955f;   // below -> surely not
        unsigned* sm = (unsigned*)dsm;  // 128 KB diag buffer (block 0)
        int warp = tid >> 5, lane = tid & 31;
        if (blk == 0 && tid == 0) s_kept = 0;
        unsigned ep = 6;
        for (int b = 0; b < NBLK; b++) {
            // -- coop phase (all blocks): diag block b + kept-rows x block-b words --
            {
                unsigned nk = *(volatile unsigned*)&g_nk;
                int nkg = ((int)nk + 31) >> 5;
                int totalw = 1024 + nkg * 32;            // warp-units
                int gw = blk * 32 + warp;
                for (int u = gw; u < totalw; u += NB * 32) {
                    int row, jw; bool vrow = true;
                    if (u < 1024) {
                        int rg = u >> 5, wl = u & 31;
                        if (wl < rg) continue;           // sub-diagonal: never read, stays 0
                        row = (b << 10) + (rg << 5) + lane;
                        jw = (b << 5) + wl;
                    } else {
                        int v2 = u - 1024;
                        int ki = ((v2 >> 5) << 5) + lane;
                        vrow = (ki < (int)nk);
                        row = vrow ? (int)*(volatile unsigned*)&g_kept[ki] : 0;
                        jw = (b << 5) + (v2 & 31);
                    }
                    float4 bb = g_top_box[row];
                    float ai = g_top_area[row];
                    const float4* jb = &g_top_box[jw << 5];
                    const float*  ja = &g_top_area[jw << 5];
                    unsigned word = 0, band = 0;
                    #pragma unroll 8
                    for (int c2 = 0; c2 < 32; c2++) {
                        float4 bj = jb[c2];              // uniform addr -> broadcast
                        float aj = ja[c2];
                        float ty  = fmaxf(bb.x, bj.x);
                        float tx  = fmaxf(bb.y, bj.y);
                        float byv = fminf(bb.z, bj.z);
                        float bxv = fminf(bb.w, bj.w);
                        float ih = fmaxf(__fsub_rn(byv, ty), 0.f);
                        float iw = fmaxf(__fsub_rn(bxv, tx), 0.f);
                        float inter = __fmul_rn(ih, iw);
                        float den = __fadd_rn(__fsub_rn(__fadd_rn(ai, aj), inter), 1e-9f);
                        bool hi = inter > __fmul_rn(BHI, den);
                        bool bd = !hi && (inter > __fmul_rn(BLO, den));
                        word |= hi ? (1u << c2) : 0u;
                        band |= bd ? (1u << c2) : 0u;
                    }
                    if (jw == (row >> 5)) {              // diagonal word: only j > row
                        unsigned dm = 0xFFFFFFFEu << (row & 31);
                        word &= dm; band &= dm;
                    }
                    if (band) {   // essentially never: exact division for ambiguous pairs
                        while (band) {
                            int c2 = __ffs(band) - 1; band &= band - 1;
                            float4 bj = jb[c2];
                            float aj = ja[c2];
                            float ty  = fmaxf(bb.x, bj.x);
                            float tx  = fmaxf(bb.y, bj.y);
                            float byv = fminf(bb.z, bj.z);
                            float bxv = fminf(bb.w, bj.w);
                            float ih = fmaxf(__fsub_rn(byv, ty), 0.f);
                            float iw = fmaxf(__fsub_rn(bxv, tx), 0.f);
                            float inter = __fmul_rn(ih, iw);
                            float den = __fadd_rn(__fsub_rn(__fadd_rn(ai, aj), inter), 1e-9f);
                            if (__fdiv_rn(inter, den) > IOUT) word |= (1u << c2);
                        }
                    }
                    if (vrow) g_mask[(size_t)row * MWORDS + jw] = word;
                }
            }
            gbar(++ep);

            // -- scan phase (block 0 only) --
            if (blk == 0) {
                if (s_kept < MAXDET) {
                    {
                        float s = g_top_score[(b << 10) + (warp << 5) + lane];
                        unsigned inval = __ballot_sync(0xffffffffu, !(s > 0.f));
                        unsigned v = 0;
                        int nk0 = s_kept;
                        for (int k = lane; k < nk0; k += 32)
                            v |= g_mask[(size_t)kept[k] * MWORDS + (b << 5) + warp];
                        v = __reduce_or_sync(0xffffffffu, v) | inval;
                        if (lane == 0) blocksup[warp] = v;
                    }
                    __syncthreads();
                    if (tid < 32) {
                        unsigned v = blocksup[lane];
                        unsigned full = __ballot_sync(0xffffffffu, v == 0xFFFFFFFFu);
                        if (lane == 0) s_skip = (full == 0xFFFFFFFFu) ? 1 : 0;
                    }
                    if (tid == 0) s_prev = s_kept;
                    __syncthreads();
                    if (!s_skip) {
                        for (int u = tid; u < 8192; u += 1024) {   // diag block -> smem
                            int i = u >> 3, w4 = u & 7;
                            ((uint4*)sm)[u] =
                                ((const uint4*)(g_mask + (size_t)((b << 10) + i) * MWORDS + (b << 5)))[w4];
                        }
                        __syncthreads();
                        if (tid < 32) {
                            unsigned sup_w = blocksup[lane];
                            int cnt = s_kept;
                            while (cnt < MAXDET) {
                                unsigned live = ~sup_w;
                                unsigned bal = __ballot_sync(0xffffffffu, live != 0u);
                                if (!bal) break;
                                int l = __ffs(bal) - 1;
                                unsigned lw = __shfl_sync(0xffffffffu, live, l);
                                int li = (l << 5) + __ffs(lw) - 1;
                                unsigned live2 = live;
                                if (lane == l) live2 &= ~(1u << (li & 31));
                                unsigned bal2 = __ballot_sync(0xffffffffu, live2 != 0u);
                                int lj = -1;
                                if (bal2) {
                                    int l2 = __ffs(bal2) - 1;
                                    unsigned lw2 = __shfl_sync(0xffffffffu, live2, l2);
                                    lj = (l2 << 5) + __ffs(lw2) - 1;
                                }
                                unsigned rowi = sm[li * 32 + lane];
                                bool pairok = false;
                                if (lj >= 0 && cnt + 1 < MAXDET) {
                                    unsigned wv = __shfl_sync(0xffffffffu, rowi, lj >> 5);
                                    pairok = ((wv >> (lj & 31)) & 1u) == 0u;
                                }
                                if (pairok) {
                                    unsigned rowj = sm[lj * 32 + lane];
                                    if (lane == 0) { kept[cnt] = (b << 10) + li; kept[cnt + 1] = (b << 10) + lj; }
                                    cnt += 2;
                                    sup_w |= rowi | rowj;
                                    if (lane == (li >> 5)) sup_w |= (1u << (li & 31));
                                    if (lane == (lj >> 5)) sup_w |= (1u << (lj & 31));
                                } else {
                                    if (lane == 0) kept[cnt] = (b << 10) + li;
                                    cnt++;
                                    sup_w |= rowi;
                                    if (lane == (li >> 5)) sup_w |= (1u << (li & 31));
                                }
                            }
                            if (lane == 0) s_kept = cnt;
                        }
                        __syncthreads();
                    }
                    // publish new keeps + status
                    for (int t = s_prev + tid; t < s_kept; t += NT)
                        g_kept[t] = (unsigned)kept[t];
                    if (tid == 0) {
                        g_nk = (unsigned)s_kept;
                        g_done = (s_kept >= MAXDET || b == NBLK - 1) ? 1u : 0u;
                    }
                } else if (tid == 0) {
                    g_done = 1u;
                }
            }
            gbar(++ep);
            if (*(volatile unsigned*)&g_done) break;
        }
    }

    // ---- output (block 0; others exit) ----
    if (blk != 0) return;
    {
        int m = s_kept;
        for (int t = tid; t < MAXDET; t += 1024) {
            float4 bx = make_float4(0.f, 0.f, 0.f, 0.f);
            float c = 0.f, s = 0.f;
            if (t < m) {
                int ki = kept[t];
                bx = g_top_box[ki];
                c = g_top_cls[ki];
                s = g_top_score[ki];
            }
            out[4 * t + 0] = bx.x; out[4 * t + 1] = bx.y;
            out[4 * t + 2] = bx.z; out[4 * t + 3] = bx.w;
            out[1200 + t] = c;
            out[1500 + t] = s;
        }
        __syncthreads();
        if (tid == 0) g_arrive = 0u;   // reset barrier for next (graph-replayed) call
    }
}

// ---------------- launch: ONE kernel node ----------------
extern "C" void kernel_launch(void* const* d_in, const int* in_sizes, int n_in,
                              void* d_out, int out_size) {
    const float* preds = (const float*)d_in[0];
    float* out = (float*)d_out;
    int n = in_sizes[0] / NFEAT;
    if (n > NA) n = NA;

    cudaFuncSetAttribute(yolo_all, cudaFuncAttributeMaxDynamicSharedMemorySize, SMEM_BYTES);
    yolo_all<<<NB, NT, SMEM_BYTES>>>(preds, out, n);
}

// round 15
// speedup vs baseline: 1.8731x; 1.0640x over previous
#include <cuda_runtime.h>

#define NA      102000
#define NFEAT   85
#define NC      80
#define KSEL    8192
#define CAP     16384
#define MAXDET  300
#define CONF    0.25f
#define IOUT    0.45f
#define MWORDS  256     // KSEL/32
#define NBLK    8       // KSEL/1024
#define NB      148     // persistent blocks (1 per SM, co-resident)
#define NT      1024
#define SMEM_BYTES 131072

// ---------------- device scratch (zero-init at load; invariants restored per call) ----
__device__ unsigned int       g_arrive;
__device__ unsigned int       g_status;         // scan progress: low16 = blocks done, bit31 = done
__device__ unsigned int       g_keys[NA];
__device__ unsigned int       g_hist1[65536];
__device__ unsigned int       g_T;
__device__ unsigned int       g_cnt;
__device__ unsigned int       g_nk;
__device__ unsigned int       g_kept[MAXDET];
__device__ unsigned long long g_surv[CAP];
__device__ int                g_rank[CAP];      // written before read each call (no zeroing needed)
__device__ float4             g_top_box[KSEL];
__device__ float              g_top_area[KSEL];
__device__ float              g_top_score[KSEL];
__device__ float              g_top_cls[KSEL];
__device__ unsigned int       g_mask[KSEL * MWORDS];   // only demanded words written; sub-diagonal stays 0

// grid-wide barrier: arrival = atomic; wait = plain volatile load (no contended RMW poll)
__device__ __forceinline__ void gbar(unsigned e) {
    __syncthreads();
    if (threadIdx.x == 0) {
        __threadfence();
        atomicAdd(&g_arrive, 1u);
        while (*(volatile unsigned*)&g_arrive < e * NB) { }
        __threadfence();
    }
    __syncthreads();
}

// 256-wide suffix-sum select (tid<256 carry data); final inclusive suffix left in sA
__device__ __forceinline__ int suffix_sel_1024(unsigned* sA, unsigned* sB, int* sres,
                                               int tid, unsigned v, unsigned target) {
    if (tid < 256) sA[tid] = v;
    __syncthreads();
    unsigned* src = sA; unsigned* dst = sB;
    #pragma unroll
    for (int d = 1; d < 256; d <<= 1) {
        unsigned x = 0;
        if (tid < 256) { x = src[tid]; if (tid + d < 256) x += src[tid + d]; }
        if (tid < 256) dst[tid] = x;
        __syncthreads();
        unsigned* t2 = src; src = dst; dst = t2;
    }   // 8 swaps -> suffix back in sA
    if (tid == 0) *sres = -1;
    __syncthreads();
    if (tid < 256 && sA[tid] >= target) atomicMax(sres, tid);
    __syncthreads();
    return *sres;
}

extern "C" __global__ void __launch_bounds__(NT, 1)
yolo_all(const float* __restrict__ preds, float* __restrict__ out, int n) {
    extern __shared__ char dsm[];
    __shared__ unsigned s_sA[256], s_sB[256];
    __shared__ int s_res;
    __shared__ int kept[MAXDET];
    __shared__ unsigned blocksup[32];
    __shared__ unsigned s_T, s_st;
    __shared__ int s_kept, s_skip, s_prev;

    int tid = threadIdx.x;
    int blk = blockIdx.x;
    int g = blk * NT + tid;

    // ---- P0: zero per-call state ----
    if (g < 65536) g_hist1[g] = 0u;
    if (g < KSEL)  g_top_score[g] = 0.f;
    if (g == 0)    { g_cnt = 0u; g_nk = 0u; g_T = 0u; g_status = 0u; }
    gbar(1);

    // ---- P1: scores via fmax tree (max is exact/order-free; *obj monotone), coarse hist ----
    {
        float*  sf  = (float*)dsm;
        float4* sf4 = (float4*)dsm;
        int ntile = (n + 255) / 256;
        for (int tile = blk; tile < ntile; tile += NB) {
            int base = tile * 256;
            int cnt_t = n - base; if (cnt_t > 256) cnt_t = 256;
            int nel = cnt_t * NFEAT;
            int nel4 = nel >> 2;
            const float*  src  = preds + (size_t)base * NFEAT;
            const float4* src4 = (const float4*)src;      // base*85*4 % 16 == 0
            __syncthreads();
            for (int i = tid; i < nel4; i += NT) sf4[i] = src4[i];
            for (int i = (nel4 << 2) + tid; i < nel; i += NT) sf[i] = src[i];
            __syncthreads();
            if (tid < cnt_t) {
                const float* p = &sf[tid * NFEAT];        // stride 85: conflict-free
                float obj = p[4];
                float m = p[5];
                #pragma unroll
                for (int c = 1; c < NC; c++) m = fmaxf(m, p[5 + c]);
                float score = (obj > CONF) ? __fmul_rn(m, obj) : 0.0f;
                unsigned key = __float_as_uint(score);
                g_keys[base + tid] = key;
                if (key) atomicAdd(&g_hist1[key >> 16], 1u);
            }
        }
    }
    gbar(2);

    // ---- P2: coarse threshold -> g_T; block 0 produces, others poll flag ----
    if (blk == 0) {
        unsigned s = 0;
        if (tid < 256) {
            const unsigned* h = g_hist1 + tid * 256;
            #pragma unroll 8
            for (int b = 0; b < 256; b++) s += h[b];
        }
        int C = suffix_sel_1024(s_sA, s_sB, &s_res, tid, s, KSEL);
        unsigned T;
        if (C < 0) {
            T = 1u;                               // fewer than KSEL positives: take all
        } else {
            unsigned A1 = (C < 255) ? s_sA[C + 1] : 0u;
            __syncthreads();
            unsigned e = (tid < 256) ? g_hist1[C * 256 + tid] : 0u;
            int b = suffix_sel_1024(s_sA, s_sB, &s_res, tid, e, (unsigned)KSEL - A1);
            T = ((unsigned)(C * 256 + b)) << 16;
            if (!T) T = 1u;                       // never admit score==0
        }
        if (tid == 0) { s_T = T; __threadfence(); g_T = T; }
        __syncthreads();
    } else {
        if (tid == 0) {
            unsigned T;
            do { T = *(volatile unsigned*)&g_T; } while (!T);
            s_T = T;
        }
        __syncthreads();
    }

    // ---- P3: compact survivors (coarse superset of top-K), warp-aggregated ----
    {
        unsigned T = s_T;
        bool pred = false; unsigned key = 0;
        if (g < n) { key = g_keys[g]; pred = (key >= T); }
        unsigned m = __ballot_sync(0xffffffffu, pred);
        if (m) {
            int lane = tid & 31;
            int leader = __ffs(m) - 1;
            unsigned base2 = 0;
            if (lane == leader) base2 = atomicAdd(&g_cnt, (unsigned)__popc(m));
            base2 = __shfl_sync(0xffffffffu, base2, leader);
            if (pred) {
                unsigned pos = base2 + (unsigned)__popc(m & ((1u << lane) - 1u));
                if (pos < CAP)
                    g_surv[pos] = ((unsigned long long)key << 32) | (unsigned)(~g);
            }
        }
    }
    gbar(3);

    // ---- P4: exact global rank; all keys smem-resident, 16-lane groups, direct store ----
    {
        unsigned long long* skeys = (unsigned long long*)dsm;   // <=128 KB
        unsigned cntu = g_cnt; if (cntu > CAP) cntu = CAP;
        int cnt = (int)cntu;
        __syncthreads();
        for (int j = tid; j < cnt; j += NT) skeys[j] = g_surv[j];
        __syncthreads();
        int lane16 = tid & 15;
        #pragma unroll
        for (int itr = 0; itr < 2; itr++) {
            int gbase = blk * 64 + itr * (NB * 64);
            if (gbase >= cnt) break;                  // block-uniform
            int gid = gbase + (tid >> 4);
            bool act = gid < cnt;
            unsigned long long key = act ? skeys[gid] : 0xFFFFFFFFFFFFFFFFULL;
            int r = 0;
            #pragma unroll 4
            for (int j = lane16; j < cnt; j += 16)
                r += (skeys[j] > key) ? 1 : 0;
            r += __shfl_xor_sync(0xffffffffu, r, 8, 16);
            r += __shfl_xor_sync(0xffffffffu, r, 4, 16);
            r += __shfl_xor_sync(0xffffffffu, r, 2, 16);
            r += __shfl_xor_sync(0xffffffffu, r, 1, 16);
            if (act && lane16 == 0) g_rank[gid] = r;
        }
    }
    gbar(4);

    // ---- P5: scatter to rank (<KSEL) + gather box/area/score + exact argmax ----
    {
        unsigned cntu = g_cnt; if (cntu > CAP) cntu = CAP;
        int cnt = (int)cntu;
        for (int c = blk; c * 256 < cnt; c += NB) {
            int i = c * 256 + tid;
            if (tid < 256 && i < cnt) {
                int r = g_rank[i];
                if (r < KSEL) {
                    unsigned long long key = g_surv[i];
                    unsigned idx = ~(unsigned)(key & 0xFFFFFFFFu);
                    float score = __uint_as_float((unsigned)(key >> 32));
                    const float* p = preds + (size_t)idx * NFEAT;
                    float x = p[0], y = p[1], w = p[2], h = p[3];
                    float hh = __fmul_rn(h, 0.5f), hw = __fmul_rn(w, 0.5f);
                    float4 box;
                    box.x = __fsub_rn(y, hh);
                    box.y = __fsub_rn(x, hw);
                    box.z = __fadd_rn(y, hh);
                    box.w = __fadd_rn(x, hw);
                    float area = __fmul_rn(__fsub_rn(box.z, box.x), __fsub_rn(box.w, box.y));
                    float obj = p[4];
                    float best = -1.0f; int bi = 0;
                    #pragma unroll 4
                    for (int cc = 0; cc < NC; cc++) {
                        float v = __fmul_rn(p[5 + cc], obj);   // exact reference argmax order
                        if (v > best) { best = v; bi = cc; }
                    }
                    g_top_box[r]   = box;
                    g_top_area[r]  = area;
                    g_top_score[r] = score;
                    g_top_cls[r]   = (float)bi;
                }
            }
        }
    }
    gbar(5);

    // ---- P6/P7 fused: lazy mask + quad-speculative scan ----
    {
        const float BHI = 0.4500045f;   // above -> surely iou>0.45 (margin >> fp32 err)
        const float BLO = 0.4499955f;   // below -> surely not
        unsigned* sm = (unsigned*)dsm;  // 128 KB diag buffer (block 0)
        int warp = tid >> 5, lane = tid & 31;
        const unsigned FULL = 0xffffffffu;
        if (blk == 0 && tid == 0) s_kept = 0;
        for (int b = 0; b < NBLK; b++) {
            // -- coop phase (all blocks): diag block b + kept-rows x block-b words --
            {
                unsigned nk = *(volatile unsigned*)&g_nk;
                int nkg = ((int)nk + 31) >> 5;
                int totalw = 1024 + nkg * 32;            // warp-units
                int gw = blk * 32 + warp;
                for (int u = gw; u < totalw; u += NB * 32) {
                    int row, jw; bool vrow = true;
                    if (u < 1024) {
                        int rg = u >> 5, wl = u & 31;
                        if (wl < rg) continue;           // sub-diagonal: never read, stays 0
                        row = (b << 10) + (rg << 5) + lane;
                        jw = (b << 5) + wl;
                    } else {
                        int v2 = u - 1024;
                        int ki = ((v2 >> 5) << 5) + lane;
                        vrow = (ki < (int)nk);
                        row = vrow ? (int)*(volatile unsigned*)&g_kept[ki] : 0;
                        jw = (b << 5) + (v2 & 31);
                    }
                    float4 bb = g_top_box[row];
                    float ai = g_top_area[row];
                    const float4* jb = &g_top_box[jw << 5];
                    const float*  ja = &g_top_area[jw << 5];
                    unsigned word = 0, band = 0;
                    #pragma unroll 8
                    for (int c2 = 0; c2 < 32; c2++) {
                        float4 bj = jb[c2];              // uniform addr -> broadcast
                        float aj = ja[c2];
                        float ty  = fmaxf(bb.x, bj.x);
                        float tx  = fmaxf(bb.y, bj.y);
                        float byv = fminf(bb.z, bj.z);
                        float bxv = fminf(bb.w, bj.w);
                        float ih = fmaxf(__fsub_rn(byv, ty), 0.f);
                        float iw = fmaxf(__fsub_rn(bxv, tx), 0.f);
                        float inter = __fmul_rn(ih, iw);
                        float den = __fadd_rn(__fsub_rn(__fadd_rn(ai, aj), inter), 1e-9f);
                        bool hi = inter > __fmul_rn(BHI, den);
                        bool bd = !hi && (inter > __fmul_rn(BLO, den));
                        word |= hi ? (1u << c2) : 0u;
                        band |= bd ? (1u << c2) : 0u;
                    }
                    if (jw == (row >> 5)) {              // diagonal word: only j > row
                        unsigned dm = 0xFFFFFFFEu << (row & 31);
                        word &= dm; band &= dm;
                    }
                    if (band) {   // essentially never: exact division for ambiguous pairs
                        while (band) {
                            int c2 = __ffs(band) - 1; band &= band - 1;
                            float4 bj = jb[c2];
                            float aj = ja[c2];
                            float ty  = fmaxf(bb.x, bj.x);
                            float tx  = fmaxf(bb.y, bj.y);
                            float byv = fminf(bb.z, bj.z);
                            float bxv = fminf(bb.w, bj.w);
                            float ih = fmaxf(__fsub_rn(byv, ty), 0.f);
                            float iw = fmaxf(__fsub_rn(bxv, tx), 0.f);
                            float inter = __fmul_rn(ih, iw);
                            float den = __fadd_rn(__fsub_rn(__fadd_rn(ai, aj), inter), 1e-9f);
                            if (__fdiv_rn(inter, den) > IOUT) word |= (1u << c2);
                        }
                    }
                    if (vrow) g_mask[(size_t)row * MWORDS + jw] = word;
                }
            }
            // -- arrival (all blocks); only block 0 waits --
            __syncthreads();
            if (tid == 0) { __threadfence(); atomicAdd(&g_arrive, 1u); }

            if (blk == 0) {
                if (tid == 0) {
                    unsigned target = (unsigned)(6 + b) * NB;
                    while (*(volatile unsigned*)&g_arrive < target) { }
                    __threadfence();
                }
                __syncthreads();
                // -- scan block b --
                if (s_kept < MAXDET) {
                    {
                        float s = g_top_score[(b << 10) + (warp << 5) + lane];
                        unsigned inval = __ballot_sync(FULL, !(s > 0.f));
                        unsigned v = 0;
                        int nk0 = s_kept;
                        for (int k = lane; k < nk0; k += 32)
                            v |= g_mask[(size_t)kept[k] * MWORDS + (b << 5) + warp];
                        v = __reduce_or_sync(FULL, v) | inval;
                        if (lane == 0) blocksup[warp] = v;
                    }
                    __syncthreads();
                    if (tid < 32) {
                        unsigned v = blocksup[lane];
                        unsigned full = __ballot_sync(FULL, v == 0xFFFFFFFFu);
                        if (lane == 0) s_skip = (full == 0xFFFFFFFFu) ? 1 : 0;
                    }
                    if (tid == 0) s_prev = s_kept;
                    __syncthreads();
                    if (!s_skip) {
                        for (int u = tid; u < 8192; u += 1024) {   // diag block -> smem
                            int i = u >> 3, w4 = u & 7;
                            ((uint4*)sm)[u] =
                                ((const uint4*)(g_mask + (size_t)((b << 10) + i) * MWORDS + (b << 5)))[w4];
                        }
                        __syncthreads();
                        if (tid < 32) {
                            unsigned sup_w = blocksup[lane];
                            int cnt = s_kept;
                            int base = b << 10;
                            while (cnt < MAXDET) {
                                unsigned live = ~sup_w;
                                unsigned bal = __ballot_sync(FULL, live != 0u);
                                if (!bal) break;
                                int l = __ffs(bal) - 1;
                                unsigned lw = __shfl_sync(FULL, live, l);
                                int c0 = (l << 5) + __ffs(lw) - 1;
                                int c1 = c0 + 1, c2 = c0 + 2, c3 = c0 + 3;
                                bool in1 = c1 < 1024, in2 = c2 < 1024, in3 = c3 < 1024;
                                unsigned r0 = sm[c0 * 32 + lane];
                                unsigned r1 = sm[(in1 ? c1 : 0) * 32 + lane];
                                unsigned r2 = sm[(in2 ? c2 : 0) * 32 + lane];
                                unsigned r3 = sm[(in3 ? c3 : 0) * 32 + lane];
                                int w1 = (c1 >> 5) & 31, w2 = (c2 >> 5) & 31, w3 = (c3 >> 5) & 31;
                                int b1 = c1 & 31, b2 = c2 & 31, b3 = c3 & 31;
                                unsigned lv1 = __shfl_sync(FULL, live, w1);
                                unsigned lv2 = __shfl_sync(FULL, live, w2);
                                unsigned lv3 = __shfl_sync(FULL, live, w3);
                                unsigned q01 = __shfl_sync(FULL, r0, w1);
                                unsigned q02 = __shfl_sync(FULL, r0, w2);
                                unsigned q03 = __shfl_sync(FULL, r0, w3);
                                unsigned q12 = __shfl_sync(FULL, r1, w2);
                                unsigned q13 = __shfl_sync(FULL, r1, w3);
                                unsigned q23 = __shfl_sync(FULL, r2, w3);
                                // sequential-greedy-exact speculation:
                                bool ok1 = in1 && ((lv1 >> b1) & 1u) && !((q01 >> b1) & 1u);
                                bool a1  = ok1 && (cnt + 1 < MAXDET);
                                bool st1 = ok1 && !a1;            // blocked only by MAXDET
                                bool ok2 = !st1 && in2 && ((lv2 >> b2) & 1u) && !((q02 >> b2) & 1u)
                                           && (!a1 || !((q12 >> b2) & 1u));
                                int  p2  = cnt + 1 + (a1 ? 1 : 0);
                                bool a2  = ok2 && (p2 < MAXDET);
                                bool st2 = ok2 && !a2;
                                bool ok3 = !st1 && !st2 && in3 && ((lv3 >> b3) & 1u) && !((q03 >> b3) & 1u)
                                           && (!a1 || !((q13 >> b3) & 1u))
                                           && (!a2 || !((q23 >> b3) & 1u));
                                int  p3  = p2 + (a2 ? 1 : 0);
                                bool a3  = ok3 && (p3 < MAXDET);
                                if (lane == 0) {
                                    kept[cnt] = base + c0;
                                    if (a1) kept[cnt + 1] = base + c1;
                                    if (a2) kept[p2] = base + c2;
                                    if (a3) kept[p3] = base + c3;
                                }
                                sup_w |= r0;
                                if (a1) sup_w |= r1;
                                if (a2) sup_w |= r2;
                                if (a3) sup_w |= r3;
                                if (lane == ((c0 >> 5) & 31)) sup_w |= 1u << (c0 & 31);
                                if (a1 && lane == w1) sup_w |= 1u << b1;
                                if (a2 && lane == w2) sup_w |= 1u << b2;
                                if (a3 && lane == w3) sup_w |= 1u << b3;
                                cnt = p3 + (a3 ? 1 : 0);
                            }
                            if (lane == 0) s_kept = cnt;
                        }
                        __syncthreads();
                    }
                    // publish new keeps, then status
                    for (int t = s_prev + tid; t < s_kept; t += NT)
                        g_kept[t] = (unsigned)kept[t];
                }
                __syncthreads();
                if (tid == 0) {
                    g_nk = (unsigned)s_kept;
                    unsigned done = (s_kept >= MAXDET || b == NBLK - 1) ? 0x80000000u : 0u;
                    __threadfence();
                    g_status = (unsigned)(b + 1) | done;
                    s_st = (unsigned)(b + 1) | done;
                }
                __syncthreads();
                if (s_st & 0x80000000u) break;
            } else {
                // non-zero blocks: poll status for this iteration
                if (tid == 0) {
                    unsigned st;
                    do { st = *(volatile unsigned*)&g_status; }
                    while ((st & 0xFFFFu) < (unsigned)(b + 1) && !(st & 0x80000000u));
                    __threadfence();
                    s_st = st;
                }
                __syncthreads();
                if (s_st & 0x80000000u) break;
            }
        }
    }

    // ---- output (block 0; others exit) ----
    if (blk != 0) return;
    {
        int m = s_kept;
        for (int t = tid; t < MAXDET; t += 1024) {
            float4 bx = make_float4(0.f, 0.f, 0.f, 0.f);
            float c = 0.f, s = 0.f;
            if (t < m) {
                int ki = kept[t];
                bx = g_top_box[ki];
                c = g_top_cls[ki];
                s = g_top_score[ki];
            }
            out[4 * t + 0] = bx.x; out[4 * t + 1] = bx.y;
            out[4 * t + 2] = bx.z; out[4 * t + 3] = bx.w;
            out[1200 + t] = c;
            out[1500 + t] = s;
        }
        __syncthreads();
        if (tid == 0) g_arrive = 0u;   // reset barrier for next (graph-replayed) call
    }
}

// ---------------- launch: ONE kernel node ----------------
extern "C" void kernel_launch(void* const* d_in, const int* in_sizes, int n_in,
                              void* d_out, int out_size) {
    const float* preds = (const float*)d_in[0];
    float* out = (float*)d_out;
    int n = in_sizes[0] / NFEAT;
    if (n > NA) n = NA;

    cudaFuncSetAttribute(yolo_all, cudaFuncAttributeMaxDynamicSharedMemorySize, SMEM_BYTES);
    yolo_all<<<NB, NT, SMEM_BYTES>>>(preds, out, n);
}